// round 9
// baseline (speedup 1.0000x reference)
#include <cuda_runtime.h>
#include <stdint.h>

#define EMBED_NUM 1024
#define EMBED_DIM 64
#define SPATIAL   32768
#define NVEC      131072
#define CHUNK     128
#define THREADS   128
#define PPT       2

// dynamic smem layout (bytes): buf0 32768 | buf1 32768 | snorm0 512 | snorm1 512
#define SM_BUF(i)  ((i) * 32768)
#define SM_SN(i)   (65536 + (i) * 512)
#define SMEM_BYTES 66560

__device__ float g_norms[EMBED_NUM];

__device__ __forceinline__ unsigned sptr(const void* p) {
    return (unsigned)__cvta_generic_to_shared(p);
}
#define CP16(d, s)  asm volatile("cp.async.cg.shared.global [%0], [%1], 16;" :: "r"(d), "l"(s) : "memory")
#define CP_COMMIT() asm volatile("cp.async.commit_group;" ::: "memory")
#define CP_WAIT0()  asm volatile("cp.async.wait_group 0;" ::: "memory")
#define FM(a, x, e) asm("fma.rn.f32x2 %0, %1, %2, %0;" : "+l"(a) : "l"(x), "l"(e))

// --------------------------------------------------------------------------
__global__ void vq_norms_kernel(const float* __restrict__ emb) {
    int j = blockIdx.x * blockDim.x + threadIdx.x;
    if (j < EMBED_NUM) {
        const float4* row = reinterpret_cast<const float4*>(emb + j * EMBED_DIM);
        float s = 0.f;
#pragma unroll
        for (int k = 0; k < EMBED_DIM / 4; k++) {
            float4 v = row[k];
            s += v.x * v.x + v.y * v.y + v.z * v.z + v.w * v.w;
        }
        g_norms[j] = s;
    }
}

// --------------------------------------------------------------------------
// One thread = 2 positions, 4 codes per inner block, cp.async double-buffered
// codebook. R9 change: FFMA2s emitted in x-major runs of 4 so the SAME x
// register occupies slot-b of 4 consecutive FFMA2s -> ptxas .reuse kills its
// RF reads -> per-bank distinct operands drop 3 -> 2 on 3 of 4 instructions
// (RF-bank rt 3 -> 2.25 avg). Chains and reduction order are bit-identical
// to the validated R3/R8 kernel: rel_err must remain exactly 0.0.
// --------------------------------------------------------------------------
__global__ __launch_bounds__(THREADS, 2)
void vq_argmin_kernel(const float* __restrict__ z,
                      const float* __restrict__ emb,
                      float* __restrict__ out) {
    extern __shared__ char smraw[];
    const unsigned sb = sptr(smraw);

    const int p0 = blockIdx.x * (THREADS * PPT) + threadIdx.x;
    const int p1 = p0 + THREADS;
    const int b  = p0 >> 15;
    const int base0 = b * (EMBED_DIM * SPATIAL) + (p0 & (SPATIAL - 1));
    const int base1 = b * (EMBED_DIM * SPATIAL) + (p1 & (SPATIAL - 1));

    // prefetch chunk 0 (+norms) while we load x
    {
        const char* src = (const char*)(emb);
        unsigned dst = sb + SM_BUF(0);
#pragma unroll
        for (int i = 0; i < 16; i++)
            CP16(dst + (threadIdx.x + i * 128) * 16, src + (threadIdx.x + i * 128) * 16);
        if (threadIdx.x < 32)
            CP16(sb + SM_SN(0) + threadIdx.x * 16, (const char*)g_norms + threadIdx.x * 16);
        CP_COMMIT();
    }

    // x for both positions -> packed f32x2 registers + xnorms (R3-identical)
    unsigned long long x0[EMBED_DIM / 2], x1[EMBED_DIM / 2];
    float xn0 = 0.f, xn1 = 0.f;
#pragma unroll
    for (int k = 0; k < EMBED_DIM; k += 2) {
        float a = z[base0 + k * SPATIAL];
        float c = z[base0 + (k + 1) * SPATIAL];
        xn0 = __fadd_rn(xn0, __fmul_rn(a, a));
        xn0 = __fadd_rn(xn0, __fmul_rn(c, c));
        asm("mov.b64 %0, {%1, %2};" : "=l"(x0[k >> 1]) : "f"(a), "f"(c));
        float d = z[base1 + k * SPATIAL];
        float e = z[base1 + (k + 1) * SPATIAL];
        xn1 = __fadd_rn(xn1, __fmul_rn(d, d));
        xn1 = __fadd_rn(xn1, __fmul_rn(e, e));
        asm("mov.b64 %0, {%1, %2};" : "=l"(x1[k >> 1]) : "f"(d), "f"(e));
    }

    float best0 = 3.4e38f, best1 = 3.4e38f;
    int   bi0 = 0, bi1 = 0;

    CP_WAIT0();
    __syncthreads();

#pragma unroll 1
    for (int c = 0; c < EMBED_NUM / CHUNK; c++) {
        if (c < EMBED_NUM / CHUNK - 1) {               // prefetch next chunk
            const char* src = (const char*)(emb + (c + 1) * CHUNK * EMBED_DIM);
            unsigned dst = sb + SM_BUF((c + 1) & 1);
#pragma unroll
            for (int i = 0; i < 16; i++)
                CP16(dst + (threadIdx.x + i * 128) * 16, src + (threadIdx.x + i * 128) * 16);
            if (threadIdx.x < 32)
                CP16(sb + SM_SN((c + 1) & 1) + threadIdx.x * 16,
                     (const char*)(g_norms + (c + 1) * CHUNK) + threadIdx.x * 16);
            CP_COMMIT();
        }
        const float4* se   = (const float4*)(smraw + SM_BUF(c & 1));
        const float*  snrm = (const float*) (smraw + SM_SN(c & 1));
        const int cbase = c * CHUNK;

#pragma unroll 1
        for (int j = 0; j < CHUNK; j += 4) {
            const ulonglong2* e0 = (const ulonglong2*)(se + (j + 0) * 16);
            const ulonglong2* e1 = (const ulonglong2*)(se + (j + 1) * 16);
            const ulonglong2* e2 = (const ulonglong2*)(se + (j + 2) * 16);
            const ulonglong2* e3 = (const ulonglong2*)(se + (j + 3) * 16);
            unsigned long long a0L = 0, a0H = 0, a1L = 0, a1H = 0;   // pos0, codes j..j+3
            unsigned long long a2L = 0, a2H = 0, a3L = 0, a3H = 0;
            unsigned long long b0L = 0, b0H = 0, b1L = 0, b1H = 0;   // pos1
            unsigned long long b2L = 0, b2H = 0, b3L = 0, b3H = 0;
#pragma unroll
            for (int q = 0; q < 16; q++) {
                ulonglong2 v0 = e0[q];                 // LDS.128 broadcast
                ulonglong2 v1 = e1[q];
                ulonglong2 v2 = e2[q];
                ulonglong2 v3 = e3[q];
                unsigned long long xa0 = x0[2 * q], xa1 = x0[2 * q + 1];
                unsigned long long xb0 = x1[2 * q], xb1 = x1[2 * q + 1];
                // x-major runs of 4: same slot-b register 4x consecutively -> .reuse
                FM(a0L, xa0, v0.x); FM(a1L, xa0, v1.x); FM(a2L, xa0, v2.x); FM(a3L, xa0, v3.x);
                FM(a0H, xa1, v0.y); FM(a1H, xa1, v1.y); FM(a2H, xa1, v2.y); FM(a3H, xa1, v3.y);
                FM(b0L, xb0, v0.x); FM(b1L, xb0, v1.x); FM(b2L, xb0, v2.x); FM(b3L, xb0, v3.x);
                FM(b0H, xb1, v0.y); FM(b1H, xb1, v1.y); FM(b2H, xb1, v2.y); FM(b3H, xb1, v3.y);
            }
            float en0 = snrm[j], en1 = snrm[j + 1], en2 = snrm[j + 2], en3 = snrm[j + 3];
            float t0, t1, t2, t3, dot, d;

#define EPI(POS_XN, POS_BEST, POS_BI, AL, AH, EN, COL)                                 \
            asm("mov.b64 {%0,%1}, %2;" : "=f"(t0), "=f"(t1) : "l"(AL));                \
            asm("mov.b64 {%0,%1}, %2;" : "=f"(t2), "=f"(t3) : "l"(AH));                \
            dot = (t0 + t1) + (t2 + t3);                                               \
            d = __fsub_rn(__fadd_rn(POS_XN, EN), __fmul_rn(2.0f, dot));                \
            if (d < POS_BEST) { POS_BEST = d; POS_BI = (COL); }

            EPI(xn0, best0, bi0, a0L, a0H, en0, cbase + j)
            EPI(xn0, best0, bi0, a1L, a1H, en1, cbase + j + 1)
            EPI(xn0, best0, bi0, a2L, a2H, en2, cbase + j + 2)
            EPI(xn0, best0, bi0, a3L, a3H, en3, cbase + j + 3)
            EPI(xn1, best1, bi1, b0L, b0H, en0, cbase + j)
            EPI(xn1, best1, bi1, b1L, b1H, en1, cbase + j + 1)
            EPI(xn1, best1, bi1, b2L, b2H, en2, cbase + j + 2)
            EPI(xn1, best1, bi1, b3L, b3H, en3, cbase + j + 3)
#undef EPI
        }
        if (c < EMBED_NUM / CHUNK - 1) CP_WAIT0();
        __syncthreads();
    }

    // gather winners (L2-resident rows) + channel-strided scatter
    const float4* er0 = (const float4*)(emb + bi0 * EMBED_DIM);
    const float4* er1 = (const float4*)(emb + bi1 * EMBED_DIM);
#pragma unroll
    for (int k = 0; k < EMBED_DIM / 4; k++) {
        float4 v = er0[k];
        out[base0 + (4 * k + 0) * SPATIAL] = v.x;
        out[base0 + (4 * k + 1) * SPATIAL] = v.y;
        out[base0 + (4 * k + 2) * SPATIAL] = v.z;
        out[base0 + (4 * k + 3) * SPATIAL] = v.w;
        float4 w = er1[k];
        out[base1 + (4 * k + 0) * SPATIAL] = w.x;
        out[base1 + (4 * k + 1) * SPATIAL] = w.y;
        out[base1 + (4 * k + 2) * SPATIAL] = w.z;
        out[base1 + (4 * k + 3) * SPATIAL] = w.w;
    }
}

// --------------------------------------------------------------------------
extern "C" void kernel_launch(void* const* d_in, const int* in_sizes, int n_in,
                              void* d_out, int out_size) {
    const float* z   = (const float*)d_in[0];
    const float* emb = (const float*)d_in[1];
    if (n_in >= 2 && in_sizes[0] == EMBED_NUM * EMBED_DIM &&
        in_sizes[1] != EMBED_NUM * EMBED_DIM) {
        z   = (const float*)d_in[1];
        emb = (const float*)d_in[0];
    }
    float* out = (float*)d_out;

    cudaFuncSetAttribute(vq_argmin_kernel,
                         cudaFuncAttributeMaxDynamicSharedMemorySize, SMEM_BYTES);
    vq_norms_kernel<<<(EMBED_NUM + 255) / 256, 256>>>(emb);
    vq_argmin_kernel<<<NVEC / (THREADS * PPT), THREADS, SMEM_BYTES>>>(z, emb, out);
}